// round 12
// baseline (speedup 1.0000x reference)
#include <cuda_runtime.h>
#include <cuda_fp16.h>
#include <cstdint>
#include <math.h>

#define BATCH 8192
#define IN_F  1024
#define OUT_F 1024
#define KDIM  6144
#define BM 64
#define BN 128
#define BK 64                      // halves per K-tile (128 B rows)
#define KTILES (KDIM / BK)         // 96
#define ROWB 128
#define A_BYTES (BM * ROWB)        // 8192
#define B_BYTES (BN * ROWB)        // 16384
#define STAGE_B (A_BYTES + B_BYTES) // 24576
#define NSTG 2
#define DYN_SMEM (NSTG * STAGE_B)  // 49152 -> 4 CTAs/SM

__device__ __half g_F[(size_t)BATCH * KDIM];
__device__ __half g_W[(size_t)OUT_F * KDIM];
__device__ float  g_bias[OUT_F];

__device__ __forceinline__ uint32_t smem_u32(const void* p) {
    uint32_t a;
    asm("{ .reg .u64 t; cvta.to.shared.u64 t, %1; cvt.u32.u64 %0, t; }" : "=r"(a) : "l"(p));
    return a;
}
__device__ __forceinline__ void cp_async16(uint32_t s, const void* g) {
    asm volatile("cp.async.cg.shared.global [%0], [%1], 16;\n" :: "r"(s), "l"(g));
}
#define CP_COMMIT() asm volatile("cp.async.commit_group;\n" ::: "memory")
#define CP_WAIT(n)  asm volatile("cp.async.wait_group %0;\n" :: "n"(n) : "memory")

__device__ __forceinline__ void ldsm4(uint32_t r[4], uint32_t addr) {
    asm volatile("ldmatrix.sync.aligned.m8n8.x4.shared.b16 {%0,%1,%2,%3}, [%4];"
                 : "=r"(r[0]), "=r"(r[1]), "=r"(r[2]), "=r"(r[3]) : "r"(addr));
}
__device__ __forceinline__ void mma16816(float c[4], const uint32_t a[4],
                                         uint32_t b0, uint32_t b1) {
    asm volatile(
        "mma.sync.aligned.m16n8k16.row.col.f32.f16.f16.f32 "
        "{%0,%1,%2,%3}, {%4,%5,%6,%7}, {%8,%9}, {%0,%1,%2,%3};\n"
        : "+f"(c[0]), "+f"(c[1]), "+f"(c[2]), "+f"(c[3])
        : "r"(a[0]), "r"(a[1]), "r"(a[2]), "r"(a[3]), "r"(b0), "r"(b1));
}

// ---- kernel 1: fused prologue (frozen) --------------------------------------
__global__ void prep_kernel(const float* __restrict__ x,
                            const float* __restrict__ bw,
                            const float* __restrict__ jc,
                            const float* __restrict__ bias) {
    const int tid = threadIdx.x;
    if (blockIdx.x < 1024) {
        const int o = blockIdx.x;
        const float* crow = jc + (size_t)o * IN_F * 6;
        const float* brow = bw + (size_t)o * IN_F;
        __half* wrow = g_W + (size_t)o * KDIM;

        float s = 0.0f;
#pragma unroll
        for (int u = 0; u < 4; u++) {
            int i = tid + u * 256;
            const float* c = crow + (size_t)i * 6;
            float c0 = c[0], c1 = c[1], c2 = c[2], c3 = c[3], c4 = c[4], c5 = c[5];
            float m1 = 2.0f * c1 - (15.0f / 14.0f) * c3 + (float)(2417.0 / 4158.0) * c5;
            float m2 = (16.0f / 15.0f) * c2 - (float)(988.0 / 945.0) * c4;
            float m3 = (4.0f / 7.0f) * c3 - (float)(5078.0 / 6237.0) * c5;
            float m4 = (float)(32.0 / 105.0) * c4;
            float m5 = (float)(16.0 / 99.0) * c5;
            s += c0 - 0.4f * c2 + (float)(8.0 / 45.0) * c4;
            wrow[i]            = __float2half_rn(m1);
            wrow[IN_F + i]     = __float2half_rn(m2);
            wrow[2 * IN_F + i] = __float2half_rn(m3);
            wrow[3 * IN_F + i] = __float2half_rn(m4);
            wrow[4 * IN_F + i] = __float2half_rn(m5);
            wrow[5 * IN_F + i] = __float2half_rn(brow[i]);
        }

        __shared__ float red[256];
        red[tid] = s;
        __syncthreads();
        for (int st = 128; st > 0; st >>= 1) {
            if (tid < st) red[tid] += red[tid + st];
            __syncthreads();
        }
        if (tid == 0) g_bias[o] = bias[o] + red[0];
    } else {
        int idx = (blockIdx.x - 1024) * 256 + tid;
        int b = idx >> 8, i4 = idx & 255;
        float4 xv = reinterpret_cast<const float4*>(x)[idx];
        float in[4] = {xv.x, xv.y, xv.z, xv.w};
        __half o[6][4];
#pragma unroll
        for (int u = 0; u < 4; u++) {
            float xs = in[u];
            float t = tanhf(xs);
            float t2 = t * t, t3 = t2 * t, t4 = t2 * t2, t5 = t4 * t;
            o[0][u] = __float2half_rn(t);  o[1][u] = __float2half_rn(t2);
            o[2][u] = __float2half_rn(t3); o[3][u] = __float2half_rn(t4);
            o[4][u] = __float2half_rn(t5);
            o[5][u] = __float2half_rn(xs / (1.0f + expf(-xs)));
        }
        __half* base = g_F + (size_t)b * KDIM + i4 * 4;
#pragma unroll
        for (int j = 0; j < 6; j++)
            *reinterpret_cast<uint2*>(base + j * IN_F) = *reinterpret_cast<uint2*>(o[j]);
    }
}

// ---- kernel 2: fp16 GEMM, 2-stage, 4 CTAs/SM --------------------------------
__global__ void __launch_bounds__(256, 4) gemm_kernel(float* __restrict__ out) {
    extern __shared__ __align__(16) char dsm[];
    const int tid = threadIdx.x, lane = tid & 31, wid = tid >> 5;
    const int wm = wid & 1, wn = wid >> 1;      // 2(m) x 4(n) warps, 32x32 tiles
    const int bn = blockIdx.x, bm = blockIdx.y;

    const __half* gA = g_F + (size_t)(bm * BM) * KDIM;
    const __half* gB = g_W + (size_t)(bn * BN) * KDIM;
    const uint32_t s0 = smem_u32(dsm);

    // ---- shared loader geometry (A uses c=0,1; B uses c=0..3, +A_BYTES) ----
    uint32_t sOff[4], gOff[4];
#pragma unroll
    for (int c = 0; c < 4; c++) {
        int chunk = tid + 256 * c;
        int row = chunk >> 3, ch = chunk & 7;
        sOff[c] = (uint32_t)(row * ROWB + ((ch ^ (row & 7)) << 4));
        gOff[c] = (uint32_t)(row * KDIM + ch * 8);
    }

    // ---- ldmatrix geometry ---------------------------------------------------
    const int frow = lane & 15;
    const int hi   = lane >> 4;
    const int sw   = lane & 7;
    uint32_t xb[4];
#pragma unroll
    for (int kk = 0; kk < 4; kk++)
        xb[kk] = (uint32_t)(((2 * kk + hi) ^ sw) << 4);
    uint32_t aRow[2], bRow[2];
#pragma unroll
    for (int mf = 0; mf < 2; mf++)
        aRow[mf] = s0 + (uint32_t)((wm * 32 + mf * 16 + frow) * ROWB);
#pragma unroll
    for (int nb = 0; nb < 2; nb++)
        bRow[nb] = s0 + (uint32_t)(A_BYTES + (wn * 32 + nb * 16 + frow) * ROWB);

    float acc[2][4][4];
#pragma unroll
    for (int i = 0; i < 2; i++)
#pragma unroll
        for (int j = 0; j < 4; j++)
#pragma unroll
            for (int r = 0; r < 4; r++) acc[i][j][r] = 0.0f;

#define FILL(s, kt) do { \
    uint32_t b_ = s0 + (s) * STAGE_B; \
    const __half* a0_ = gA + (size_t)(kt) * BK; \
    const __half* b0_ = gB + (size_t)(kt) * BK; \
    _Pragma("unroll") \
    for (int c_ = 0; c_ < 2; c_++) cp_async16(b_ + sOff[c_], a0_ + gOff[c_]); \
    _Pragma("unroll") \
    for (int c_ = 0; c_ < 4; c_++) cp_async16(b_ + A_BYTES + sOff[c_], b0_ + gOff[c_]); \
    CP_COMMIT(); \
} while (0)

    uint32_t af[2][4], bf[2][4];

#define STEP(kk, soff) do { \
    _Pragma("unroll") \
    for (int mf_ = 0; mf_ < 2; mf_++) ldsm4(af[mf_], aRow[mf_] + (soff) + xb[kk]); \
    _Pragma("unroll") \
    for (int nb_ = 0; nb_ < 2; nb_++) ldsm4(bf[nb_], bRow[nb_] + (soff) + xb[kk]); \
    _Pragma("unroll") \
    for (int mf_ = 0; mf_ < 2; mf_++) \
        _Pragma("unroll") \
        for (int nf_ = 0; nf_ < 4; nf_++) \
            mma16816(acc[mf_][nf_], af[mf_], \
                     bf[nf_ >> 1][nf_ & 1], bf[nf_ >> 1][(nf_ & 1) + 2]); \
} while (0)

    FILL(0, 0);

#pragma unroll 1
    for (int kt = 0; kt < KTILES; kt++) {
        CP_WAIT(0);
        __syncthreads();
        if (kt + 1 < KTILES) FILL((kt + 1) & 1, kt + 1);

        const uint32_t soff = (uint32_t)((kt & 1) * STAGE_B);
        STEP(0, soff);
        STEP(1, soff);
        STEP(2, soff);
        STEP(3, soff);
    }

    // ---- epilogue ---------------------------------------------------------------
#pragma unroll
    for (int mf = 0; mf < 2; mf++) {
        int r0 = bm * BM + wm * 32 + mf * 16 + (lane >> 2);
#pragma unroll
        for (int nf = 0; nf < 4; nf++) {
            int col = bn * BN + wn * 32 + nf * 8 + (lane & 3) * 2;
            float2 bv = *reinterpret_cast<const float2*>(&g_bias[col]);
            float2 v0 = make_float2(acc[mf][nf][0] + bv.x, acc[mf][nf][1] + bv.y);
            float2 v1 = make_float2(acc[mf][nf][2] + bv.x, acc[mf][nf][3] + bv.y);
            *reinterpret_cast<float2*>(out + (size_t)r0 * OUT_F + col)       = v0;
            *reinterpret_cast<float2*>(out + (size_t)(r0 + 8) * OUT_F + col) = v1;
        }
    }
}

// ---------------- launch ----------------------------------------------------
extern "C" void kernel_launch(void* const* d_in, const int* in_sizes, int n_in,
                              void* d_out, int out_size) {
    (void)in_sizes; (void)n_in; (void)out_size;
    const float* x    = (const float*)d_in[0];
    const float* bw   = (const float*)d_in[1];
    const float* jc   = (const float*)d_in[2];
    const float* bias = (const float*)d_in[3];
    float* out = (float*)d_out;

    cudaFuncSetAttribute(gemm_kernel, cudaFuncAttributeMaxDynamicSharedMemorySize, DYN_SMEM);

    prep_kernel<<<1024 + (BATCH * IN_F / 4) / 256, 256>>>(x, bw, jc, bias);
    dim3 grid(OUT_F / BN, BATCH / BM);   // (8, 128) = 1024 CTAs
    gemm_kernel<<<grid, 256, DYN_SMEM>>>(out);
}

// round 13
// speedup vs baseline: 1.0072x; 1.0072x over previous
#include <cuda_runtime.h>
#include <cuda_fp16.h>
#include <cstdint>
#include <math.h>

#define BATCH 8192
#define IN_F  1024
#define OUT_F 1024
#define KDIM  6144
#define BM 64
#define BN 128
#define BK 64                      // halves per K-tile (128 B rows)
#define KTILES (KDIM / BK)         // 96
#define ROWB 128
#define A_BYTES (BM * ROWB)        // 8192
#define B_BYTES (BN * ROWB)        // 16384
#define STAGE_B (A_BYTES + B_BYTES) // 24576
#define NSTG 3
#define DYN_SMEM (NSTG * STAGE_B)  // 73728 -> 3 CTAs/SM

__device__ __half g_F[(size_t)BATCH * KDIM];
__device__ __half g_W[(size_t)OUT_F * KDIM];
__device__ float  g_bias[OUT_F];

__device__ __forceinline__ uint32_t smem_u32(const void* p) {
    uint32_t a;
    asm("{ .reg .u64 t; cvta.to.shared.u64 t, %1; cvt.u32.u64 %0, t; }" : "=r"(a) : "l"(p));
    return a;
}
__device__ __forceinline__ void cp_async16(uint32_t s, const void* g) {
    asm volatile("cp.async.cg.shared.global [%0], [%1], 16;\n" :: "r"(s), "l"(g));
}
#define CP_COMMIT() asm volatile("cp.async.commit_group;\n" ::: "memory")
#define CP_WAIT(n)  asm volatile("cp.async.wait_group %0;\n" :: "n"(n) : "memory")

__device__ __forceinline__ void ldsm4(uint32_t r[4], uint32_t addr) {
    asm volatile("ldmatrix.sync.aligned.m8n8.x4.shared.b16 {%0,%1,%2,%3}, [%4];"
                 : "=r"(r[0]), "=r"(r[1]), "=r"(r[2]), "=r"(r[3]) : "r"(addr));
}
__device__ __forceinline__ void mma16816(float c[4], const uint32_t a[4],
                                         uint32_t b0, uint32_t b1) {
    asm volatile(
        "mma.sync.aligned.m16n8k16.row.col.f32.f16.f16.f32 "
        "{%0,%1,%2,%3}, {%4,%5,%6,%7}, {%8,%9}, {%0,%1,%2,%3};\n"
        : "+f"(c[0]), "+f"(c[1]), "+f"(c[2]), "+f"(c[3])
        : "r"(a[0]), "r"(a[1]), "r"(a[2]), "r"(a[3]), "r"(b0), "r"(b1));
}

// ---- kernel 1: fused prologue ------------------------------------------------
// blocks [0,1024): pack W' row + bias fold.  blocks [1024+): features, 8 elem/thr
__global__ void prep_kernel(const float* __restrict__ x,
                            const float* __restrict__ bw,
                            const float* __restrict__ jc,
                            const float* __restrict__ bias) {
    const int tid = threadIdx.x;
    if (blockIdx.x < 1024) {
        const int o = blockIdx.x;
        const float* crow = jc + (size_t)o * IN_F * 6;
        const float* brow = bw + (size_t)o * IN_F;
        __half* wrow = g_W + (size_t)o * KDIM;

        float s = 0.0f;
#pragma unroll
        for (int u = 0; u < 4; u++) {
            int i = tid + u * 256;
            const float* c = crow + (size_t)i * 6;
            float c0 = c[0], c1 = c[1], c2 = c[2], c3 = c[3], c4 = c[4], c5 = c[5];
            float m1 = 2.0f * c1 - (15.0f / 14.0f) * c3 + (float)(2417.0 / 4158.0) * c5;
            float m2 = (16.0f / 15.0f) * c2 - (float)(988.0 / 945.0) * c4;
            float m3 = (4.0f / 7.0f) * c3 - (float)(5078.0 / 6237.0) * c5;
            float m4 = (float)(32.0 / 105.0) * c4;
            float m5 = (float)(16.0 / 99.0) * c5;
            s += c0 - 0.4f * c2 + (float)(8.0 / 45.0) * c4;
            wrow[i]            = __float2half_rn(m1);
            wrow[IN_F + i]     = __float2half_rn(m2);
            wrow[2 * IN_F + i] = __float2half_rn(m3);
            wrow[3 * IN_F + i] = __float2half_rn(m4);
            wrow[4 * IN_F + i] = __float2half_rn(m5);
            wrow[5 * IN_F + i] = __float2half_rn(brow[i]);
        }

        __shared__ float red[256];
        red[tid] = s;
        __syncthreads();
        for (int st = 128; st > 0; st >>= 1) {
            if (tid < st) red[tid] += red[tid + st];
            __syncthreads();
        }
        if (tid == 0) g_bias[o] = bias[o] + red[0];
    } else {
        // 8 elements per thread -> 16B stores. idx over BATCH*128 groups.
        int idx = (blockIdx.x - 1024) * 256 + tid;
        int b = idx >> 7, i8 = idx & 127;
        const float4* xp = reinterpret_cast<const float4*>(x) + ((size_t)b << 8) + i8 * 2;
        float4 x0 = xp[0], x1 = xp[1];
        float in[8] = {x0.x, x0.y, x0.z, x0.w, x1.x, x1.y, x1.z, x1.w};
        __half o[6][8];
#pragma unroll
        for (int u = 0; u < 8; u++) {
            float xs = in[u];
            float t = tanhf(xs);
            float t2 = t * t, t3 = t2 * t, t4 = t2 * t2, t5 = t4 * t;
            o[0][u] = __float2half_rn(t);  o[1][u] = __float2half_rn(t2);
            o[2][u] = __float2half_rn(t3); o[3][u] = __float2half_rn(t4);
            o[4][u] = __float2half_rn(t5);
            o[5][u] = __float2half_rn(xs / (1.0f + expf(-xs)));
        }
        __half* base = g_F + (size_t)b * KDIM + i8 * 8;
#pragma unroll
        for (int j = 0; j < 6; j++)
            *reinterpret_cast<uint4*>(base + j * IN_F) = *reinterpret_cast<uint4*>(o[j]);
    }
}

// ---- kernel 2: fp16 GEMM, 3-stage, occ 3 (best measured config) -------------
__global__ void __launch_bounds__(256, 3) gemm_kernel(float* __restrict__ out) {
    extern __shared__ __align__(16) char dsm[];
    const int tid = threadIdx.x, lane = tid & 31, wid = tid >> 5;
    const int wm = wid & 1, wn = wid >> 1;      // 2(m) x 4(n) warps, 32x32 tiles
    const int bn = blockIdx.x, bm = blockIdx.y;

    const __half* gA = g_F + (size_t)(bm * BM) * KDIM;
    const __half* gB = g_W + (size_t)(bn * BN) * KDIM;
    const uint32_t s0 = smem_u32(dsm);

    // ---- shared loader geometry (A uses c=0,1; B uses c=0..3 at +A_BYTES) --
    uint32_t sOff[4], gOff[4];
#pragma unroll
    for (int c = 0; c < 4; c++) {
        int chunk = tid + 256 * c;
        int row = chunk >> 3, ch = chunk & 7;
        sOff[c] = (uint32_t)(row * ROWB + ((ch ^ (row & 7)) << 4));
        gOff[c] = (uint32_t)(row * KDIM + ch * 8);
    }

    // ---- ldmatrix geometry ---------------------------------------------------
    const int frow = lane & 15;
    const int hi   = lane >> 4;
    const int sw   = lane & 7;
    uint32_t xb[4];
#pragma unroll
    for (int kk = 0; kk < 4; kk++)
        xb[kk] = (uint32_t)(((2 * kk + hi) ^ sw) << 4);
    uint32_t aRow[2], bRow[2];
#pragma unroll
    for (int mf = 0; mf < 2; mf++)
        aRow[mf] = s0 + (uint32_t)((wm * 32 + mf * 16 + frow) * ROWB);
#pragma unroll
    for (int nb = 0; nb < 2; nb++)
        bRow[nb] = s0 + (uint32_t)(A_BYTES + (wn * 32 + nb * 16 + frow) * ROWB);

    float acc[2][4][4];
#pragma unroll
    for (int i = 0; i < 2; i++)
#pragma unroll
        for (int j = 0; j < 4; j++)
#pragma unroll
            for (int r = 0; r < 4; r++) acc[i][j][r] = 0.0f;

#define FILL(s, kt) do { \
    uint32_t b_ = s0 + (s) * STAGE_B; \
    const __half* a0_ = gA + (size_t)(kt) * BK; \
    const __half* b0_ = gB + (size_t)(kt) * BK; \
    _Pragma("unroll") \
    for (int c_ = 0; c_ < 2; c_++) cp_async16(b_ + sOff[c_], a0_ + gOff[c_]); \
    _Pragma("unroll") \
    for (int c_ = 0; c_ < 4; c_++) cp_async16(b_ + A_BYTES + sOff[c_], b0_ + gOff[c_]); \
    CP_COMMIT(); \
} while (0)

    uint32_t af[2][4], bf[2][4];

#define STEP(kk, soff) do { \
    _Pragma("unroll") \
    for (int mf_ = 0; mf_ < 2; mf_++) ldsm4(af[mf_], aRow[mf_] + (soff) + xb[kk]); \
    _Pragma("unroll") \
    for (int nb_ = 0; nb_ < 2; nb_++) ldsm4(bf[nb_], bRow[nb_] + (soff) + xb[kk]); \
    _Pragma("unroll") \
    for (int mf_ = 0; mf_ < 2; mf_++) \
        _Pragma("unroll") \
        for (int nf_ = 0; nf_ < 4; nf_++) \
            mma16816(acc[mf_][nf_], af[mf_], \
                     bf[nf_ >> 1][nf_ & 1], bf[nf_ >> 1][(nf_ & 1) + 2]); \
} while (0)

    FILL(0, 0);
    FILL(1, 1);

#pragma unroll 1
    for (int kt = 0; kt < KTILES; kt++) {
        if (kt == KTILES - 1) { CP_WAIT(0); } else { CP_WAIT(1); }
        __syncthreads();
        if (kt + 2 < KTILES) FILL((kt + 2) % NSTG, kt + 2);

        const uint32_t soff = (uint32_t)((kt % NSTG) * STAGE_B);
        STEP(0, soff);
        STEP(1, soff);
        STEP(2, soff);
        STEP(3, soff);
    }

    // ---- epilogue ---------------------------------------------------------------
#pragma unroll
    for (int mf = 0; mf < 2; mf++) {
        int r0 = bm * BM + wm * 32 + mf * 16 + (lane >> 2);
#pragma unroll
        for (int nf = 0; nf < 4; nf++) {
            int col = bn * BN + wn * 32 + nf * 8 + (lane & 3) * 2;
            float2 bv = *reinterpret_cast<const float2*>(&g_bias[col]);
            float2 v0 = make_float2(acc[mf][nf][0] + bv.x, acc[mf][nf][1] + bv.y);
            float2 v1 = make_float2(acc[mf][nf][2] + bv.x, acc[mf][nf][3] + bv.y);
            *reinterpret_cast<float2*>(out + (size_t)r0 * OUT_F + col)       = v0;
            *reinterpret_cast<float2*>(out + (size_t)(r0 + 8) * OUT_F + col) = v1;
        }
    }
}

// ---------------- launch ----------------------------------------------------
extern "C" void kernel_launch(void* const* d_in, const int* in_sizes, int n_in,
                              void* d_out, int out_size) {
    (void)in_sizes; (void)n_in; (void)out_size;
    const float* x    = (const float*)d_in[0];
    const float* bw   = (const float*)d_in[1];
    const float* jc   = (const float*)d_in[2];
    const float* bias = (const float*)d_in[3];
    float* out = (float*)d_out;

    cudaFuncSetAttribute(gemm_kernel, cudaFuncAttributeMaxDynamicSharedMemorySize, DYN_SMEM);

    prep_kernel<<<1024 + (BATCH * IN_F / 8) / 256, 256>>>(x, bw, jc, bias);
    dim3 grid(OUT_F / BN, BATCH / BM);   // (8, 128) = 1024 CTAs
    gemm_kernel<<<grid, 256, DYN_SMEM>>>(out);
}

// round 14
// speedup vs baseline: 1.0075x; 1.0003x over previous
#include <cuda_runtime.h>
#include <cuda_fp16.h>
#include <cstdint>
#include <math.h>

#define BATCH 8192
#define IN_F  1024
#define OUT_F 1024
#define KDIM  6144
#define BM 64
#define BN 128
#define BK 64                      // halves per K-tile (128 B rows)
#define KTILES (KDIM / BK)         // 96
#define ROWB 128
#define A_BYTES (BM * ROWB)        // 8192
#define B_BYTES (BN * ROWB)        // 16384
#define STAGE_B (A_BYTES + B_BYTES) // 24576
#define NSTG 3
#define DYN_SMEM (NSTG * STAGE_B)  // 73728 -> 3 CTAs/SM

__device__ __half g_F[(size_t)BATCH * KDIM];
__device__ __half g_W[(size_t)OUT_F * KDIM];
__device__ float  g_bias[OUT_F];

__device__ __forceinline__ uint32_t smem_u32(const void* p) {
    uint32_t a;
    asm("{ .reg .u64 t; cvta.to.shared.u64 t, %1; cvt.u32.u64 %0, t; }" : "=r"(a) : "l"(p));
    return a;
}
__device__ __forceinline__ void cp_async16(uint32_t s, const void* g) {
    asm volatile("cp.async.cg.shared.global [%0], [%1], 16;\n" :: "r"(s), "l"(g));
}
#define CP_COMMIT() asm volatile("cp.async.commit_group;\n" ::: "memory")
#define CP_WAIT(n)  asm volatile("cp.async.wait_group %0;\n" :: "n"(n) : "memory")

__device__ __forceinline__ void ldsm4(uint32_t r[4], uint32_t addr) {
    asm volatile("ldmatrix.sync.aligned.m8n8.x4.shared.b16 {%0,%1,%2,%3}, [%4];"
                 : "=r"(r[0]), "=r"(r[1]), "=r"(r[2]), "=r"(r[3]) : "r"(addr));
}
__device__ __forceinline__ void mma16816(float c[4], const uint32_t a[4],
                                         uint32_t b0, uint32_t b1) {
    asm volatile(
        "mma.sync.aligned.m16n8k16.row.col.f32.f16.f16.f32 "
        "{%0,%1,%2,%3}, {%4,%5,%6,%7}, {%8,%9}, {%0,%1,%2,%3};\n"
        : "+f"(c[0]), "+f"(c[1]), "+f"(c[2]), "+f"(c[3])
        : "r"(a[0]), "r"(a[1]), "r"(a[2]), "r"(a[3]), "r"(b0), "r"(b1));
}

// ---- kernel 1: fused prologue (R13 version — best measured) ----------------
__global__ void prep_kernel(const float* __restrict__ x,
                            const float* __restrict__ bw,
                            const float* __restrict__ jc,
                            const float* __restrict__ bias) {
    const int tid = threadIdx.x;
    if (blockIdx.x < 1024) {
        const int o = blockIdx.x;
        const float* crow = jc + (size_t)o * IN_F * 6;
        const float* brow = bw + (size_t)o * IN_F;
        __half* wrow = g_W + (size_t)o * KDIM;

        float s = 0.0f;
#pragma unroll
        for (int u = 0; u < 4; u++) {
            int i = tid + u * 256;
            const float* c = crow + (size_t)i * 6;
            float c0 = c[0], c1 = c[1], c2 = c[2], c3 = c[3], c4 = c[4], c5 = c[5];
            float m1 = 2.0f * c1 - (15.0f / 14.0f) * c3 + (float)(2417.0 / 4158.0) * c5;
            float m2 = (16.0f / 15.0f) * c2 - (float)(988.0 / 945.0) * c4;
            float m3 = (4.0f / 7.0f) * c3 - (float)(5078.0 / 6237.0) * c5;
            float m4 = (float)(32.0 / 105.0) * c4;
            float m5 = (float)(16.0 / 99.0) * c5;
            s += c0 - 0.4f * c2 + (float)(8.0 / 45.0) * c4;
            wrow[i]            = __float2half_rn(m1);
            wrow[IN_F + i]     = __float2half_rn(m2);
            wrow[2 * IN_F + i] = __float2half_rn(m3);
            wrow[3 * IN_F + i] = __float2half_rn(m4);
            wrow[4 * IN_F + i] = __float2half_rn(m5);
            wrow[5 * IN_F + i] = __float2half_rn(brow[i]);
        }

        __shared__ float red[256];
        red[tid] = s;
        __syncthreads();
        for (int st = 128; st > 0; st >>= 1) {
            if (tid < st) red[tid] += red[tid + st];
            __syncthreads();
        }
        if (tid == 0) g_bias[o] = bias[o] + red[0];
    } else {
        int idx = (blockIdx.x - 1024) * 256 + tid;
        int b = idx >> 7, i8 = idx & 127;
        const float4* xp = reinterpret_cast<const float4*>(x) + ((size_t)b << 8) + i8 * 2;
        float4 x0 = xp[0], x1 = xp[1];
        float in[8] = {x0.x, x0.y, x0.z, x0.w, x1.x, x1.y, x1.z, x1.w};
        __half o[6][8];
#pragma unroll
        for (int u = 0; u < 8; u++) {
            float xs = in[u];
            float t = tanhf(xs);
            float t2 = t * t, t3 = t2 * t, t4 = t2 * t2, t5 = t4 * t;
            o[0][u] = __float2half_rn(t);  o[1][u] = __float2half_rn(t2);
            o[2][u] = __float2half_rn(t3); o[3][u] = __float2half_rn(t4);
            o[4][u] = __float2half_rn(t5);
            o[5][u] = __float2half_rn(xs / (1.0f + expf(-xs)));
        }
        __half* base = g_F + (size_t)b * KDIM + i8 * 8;
#pragma unroll
        for (int j = 0; j < 6; j++)
            *reinterpret_cast<uint4*>(base + j * IN_F) = *reinterpret_cast<uint4*>(o[j]);
    }
}

// ---- kernel 2: fp16 GEMM — R10 verbatim (best measured: 284.5 us) ----------
__global__ void __launch_bounds__(256, 3) gemm_kernel(float* __restrict__ out) {
    extern __shared__ __align__(16) char dsm[];
    const int tid = threadIdx.x, lane = tid & 31, wid = tid >> 5;
    const int wm = wid & 1, wn = wid >> 1;      // 2(m) x 4(n) warps, 32x32 tiles
    const int bn = blockIdx.x, bm = blockIdx.y;

    const __half* gA = g_F + (size_t)(bm * BM) * KDIM;
    const __half* gB = g_W + (size_t)(bn * BN) * KDIM;
    const uint32_t s0 = smem_u32(dsm);

    // ---- loader geometry ----------------------------------------------------
    uint32_t sAoff[2], sBoff[4];
    uint32_t gAoff[2], gBoff[4];
#pragma unroll
    for (int c = 0; c < 2; c++) {
        int chunk = tid + 256 * c;
        int row = chunk >> 3, ch = chunk & 7;
        sAoff[c] = (uint32_t)(row * ROWB + ((ch ^ (row & 7)) << 4));
        gAoff[c] = (uint32_t)(row * KDIM + ch * 8);
    }
#pragma unroll
    for (int c = 0; c < 4; c++) {
        int chunk = tid + 256 * c;
        int row = chunk >> 3, ch = chunk & 7;
        sBoff[c] = (uint32_t)(A_BYTES + row * ROWB + ((ch ^ (row & 7)) << 4));
        gBoff[c] = (uint32_t)(row * KDIM + ch * 8);
    }

    // ---- ldmatrix geometry ----------------------------------------------------
    const int frow = lane & 15;
    const int hi   = lane >> 4;
    const int sw   = lane & 7;
    uint32_t xb[4];
#pragma unroll
    for (int kk = 0; kk < 4; kk++)
        xb[kk] = (uint32_t)(((2 * kk + hi) ^ sw) << 4);
    uint32_t aRow[2], bRow[2];
#pragma unroll
    for (int mf = 0; mf < 2; mf++)
        aRow[mf] = s0 + (uint32_t)((wm * 32 + mf * 16 + frow) * ROWB);
#pragma unroll
    for (int nb = 0; nb < 2; nb++)
        bRow[nb] = s0 + (uint32_t)(A_BYTES + (wn * 32 + nb * 16 + frow) * ROWB);

    float acc[2][4][4];
#pragma unroll
    for (int i = 0; i < 2; i++)
#pragma unroll
        for (int j = 0; j < 4; j++)
#pragma unroll
            for (int r = 0; r < 4; r++) acc[i][j][r] = 0.0f;

#define FILL(s, kt) do { \
    uint32_t b_ = s0 + (s) * STAGE_B; \
    const __half* a0_ = gA + (size_t)(kt) * BK; \
    const __half* b0_ = gB + (size_t)(kt) * BK; \
    _Pragma("unroll") \
    for (int c_ = 0; c_ < 2; c_++) cp_async16(b_ + sAoff[c_], a0_ + gAoff[c_]); \
    _Pragma("unroll") \
    for (int c_ = 0; c_ < 4; c_++) cp_async16(b_ + sBoff[c_], b0_ + gBoff[c_]); \
    CP_COMMIT(); \
} while (0)

    uint32_t af[2][4], bf[2][4];

#define STEP(kk, soff) do { \
    _Pragma("unroll") \
    for (int mf_ = 0; mf_ < 2; mf_++) ldsm4(af[mf_], aRow[mf_] + (soff) + xb[kk]); \
    _Pragma("unroll") \
    for (int nb_ = 0; nb_ < 2; nb_++) ldsm4(bf[nb_], bRow[nb_] + (soff) + xb[kk]); \
    _Pragma("unroll") \
    for (int mf_ = 0; mf_ < 2; mf_++) \
        _Pragma("unroll") \
        for (int nf_ = 0; nf_ < 4; nf_++) \
            mma16816(acc[mf_][nf_], af[mf_], \
                     bf[nf_ >> 1][nf_ & 1], bf[nf_ >> 1][(nf_ & 1) + 2]); \
} while (0)

    FILL(0, 0);
    FILL(1, 1);

#pragma unroll 1
    for (int kt = 0; kt < KTILES; kt++) {
        if (kt == KTILES - 1) { CP_WAIT(0); } else { CP_WAIT(1); }
        __syncthreads();
        if (kt + 2 < KTILES) FILL((kt + 2) % NSTG, kt + 2);

        const uint32_t soff = (uint32_t)((kt % NSTG) * STAGE_B);
        STEP(0, soff);
        STEP(1, soff);
        STEP(2, soff);
        STEP(3, soff);
    }

    // ---- epilogue ---------------------------------------------------------------
#pragma unroll
    for (int mf = 0; mf < 2; mf++) {
        int r0 = bm * BM + wm * 32 + mf * 16 + (lane >> 2);
#pragma unroll
        for (int nf = 0; nf < 4; nf++) {
            int col = bn * BN + wn * 32 + nf * 8 + (lane & 3) * 2;
            float2 bv = *reinterpret_cast<const float2*>(&g_bias[col]);
            float2 v0 = make_float2(acc[mf][nf][0] + bv.x, acc[mf][nf][1] + bv.y);
            float2 v1 = make_float2(acc[mf][nf][2] + bv.x, acc[mf][nf][3] + bv.y);
            *reinterpret_cast<float2*>(out + (size_t)r0 * OUT_F + col)       = v0;
            *reinterpret_cast<float2*>(out + (size_t)(r0 + 8) * OUT_F + col) = v1;
        }
    }
}

// ---------------- launch ----------------------------------------------------
extern "C" void kernel_launch(void* const* d_in, const int* in_sizes, int n_in,
                              void* d_out, int out_size) {
    (void)in_sizes; (void)n_in; (void)out_size;
    const float* x    = (const float*)d_in[0];
    const float* bw   = (const float*)d_in[1];
    const float* jc   = (const float*)d_in[2];
    const float* bias = (const float*)d_in[3];
    float* out = (float*)d_out;

    cudaFuncSetAttribute(gemm_kernel, cudaFuncAttributeMaxDynamicSharedMemorySize, DYN_SMEM);

    prep_kernel<<<1024 + (BATCH * IN_F / 8) / 256, 256>>>(x, bw, jc, bias);
    dim3 grid(OUT_F / BN, BATCH / BM);   // (8, 128) = 1024 CTAs
    gemm_kernel<<<grid, 256, DYN_SMEM>>>(out);
}

// round 15
// speedup vs baseline: 1.0194x; 1.0119x over previous
#include <cuda_runtime.h>
#include <cuda_fp16.h>
#include <cstdint>
#include <math.h>

#define BATCH 8192
#define IN_F  1024
#define OUT_F 1024
#define KDIM  6144
#define BM 64
#define BN 128
#define BK 64                      // halves per K-tile (128 B rows)
#define KTILES (KDIM / BK)         // 96
#define ROWB 128
#define A_BYTES (BM * ROWB)        // 8192
#define B_BYTES (BN * ROWB)        // 16384
#define STAGE_B (A_BYTES + B_BYTES) // 24576
#define NSTG 3
#define DYN_SMEM (NSTG * STAGE_B)  // 73728

__device__ __half g_F[(size_t)BATCH * KDIM];
__device__ __half g_W[(size_t)OUT_F * KDIM];
__device__ float  g_bias[OUT_F];

__device__ __forceinline__ uint32_t smem_u32(const void* p) {
    uint32_t a;
    asm("{ .reg .u64 t; cvta.to.shared.u64 t, %1; cvt.u32.u64 %0, t; }" : "=r"(a) : "l"(p));
    return a;
}
__device__ __forceinline__ void cp_async16(uint32_t s, const void* g) {
    asm volatile("cp.async.cg.shared.global [%0], [%1], 16;\n" :: "r"(s), "l"(g));
}
#define CP_COMMIT() asm volatile("cp.async.commit_group;\n" ::: "memory")
#define CP_WAIT(n)  asm volatile("cp.async.wait_group %0;\n" :: "n"(n) : "memory")

__device__ __forceinline__ void ldsm4(uint32_t r[4], uint32_t addr) {
    asm volatile("ldmatrix.sync.aligned.m8n8.x4.shared.b16 {%0,%1,%2,%3}, [%4];"
                 : "=r"(r[0]), "=r"(r[1]), "=r"(r[2]), "=r"(r[3]) : "r"(addr));
}
__device__ __forceinline__ void mma16816(float c[4], const uint32_t a[4],
                                         uint32_t b0, uint32_t b1) {
    asm volatile(
        "mma.sync.aligned.m16n8k16.row.col.f32.f16.f16.f32 "
        "{%0,%1,%2,%3}, {%4,%5,%6,%7}, {%8,%9}, {%0,%1,%2,%3};\n"
        : "+f"(c[0]), "+f"(c[1]), "+f"(c[2]), "+f"(c[3])
        : "r"(a[0]), "r"(a[1]), "r"(a[2]), "r"(a[3]), "r"(b0), "r"(b1));
}

// ---- kernel 1: fused prologue (frozen) --------------------------------------
__global__ void prep_kernel(const float* __restrict__ x,
                            const float* __restrict__ bw,
                            const float* __restrict__ jc,
                            const float* __restrict__ bias) {
    const int tid = threadIdx.x;
    if (blockIdx.x < 1024) {
        const int o = blockIdx.x;
        const float* crow = jc + (size_t)o * IN_F * 6;
        const float* brow = bw + (size_t)o * IN_F;
        __half* wrow = g_W + (size_t)o * KDIM;

        float s = 0.0f;
#pragma unroll
        for (int u = 0; u < 4; u++) {
            int i = tid + u * 256;
            const float* c = crow + (size_t)i * 6;
            float c0 = c[0], c1 = c[1], c2 = c[2], c3 = c[3], c4 = c[4], c5 = c[5];
            float m1 = 2.0f * c1 - (15.0f / 14.0f) * c3 + (float)(2417.0 / 4158.0) * c5;
            float m2 = (16.0f / 15.0f) * c2 - (float)(988.0 / 945.0) * c4;
            float m3 = (4.0f / 7.0f) * c3 - (float)(5078.0 / 6237.0) * c5;
            float m4 = (float)(32.0 / 105.0) * c4;
            float m5 = (float)(16.0 / 99.0) * c5;
            s += c0 - 0.4f * c2 + (float)(8.0 / 45.0) * c4;
            wrow[i]            = __float2half_rn(m1);
            wrow[IN_F + i]     = __float2half_rn(m2);
            wrow[2 * IN_F + i] = __float2half_rn(m3);
            wrow[3 * IN_F + i] = __float2half_rn(m4);
            wrow[4 * IN_F + i] = __float2half_rn(m5);
            wrow[5 * IN_F + i] = __float2half_rn(brow[i]);
        }

        __shared__ float red[256];
        red[tid] = s;
        __syncthreads();
        for (int st = 128; st > 0; st >>= 1) {
            if (tid < st) red[tid] += red[tid + st];
            __syncthreads();
        }
        if (tid == 0) g_bias[o] = bias[o] + red[0];
    } else {
        int idx = (blockIdx.x - 1024) * 256 + tid;
        int b = idx >> 8, i4 = idx & 255;
        float4 xv = reinterpret_cast<const float4*>(x)[idx];
        float in[4] = {xv.x, xv.y, xv.z, xv.w};
        __half o[6][4];
#pragma unroll
        for (int u = 0; u < 4; u++) {
            float xs = in[u];
            float t = tanhf(xs);
            float t2 = t * t, t3 = t2 * t, t4 = t2 * t2, t5 = t4 * t;
            o[0][u] = __float2half_rn(t);  o[1][u] = __float2half_rn(t2);
            o[2][u] = __float2half_rn(t3); o[3][u] = __float2half_rn(t4);
            o[4][u] = __float2half_rn(t5);
            o[5][u] = __float2half_rn(xs / (1.0f + expf(-xs)));
        }
        __half* base = g_F + (size_t)b * KDIM + i4 * 4;
#pragma unroll
        for (int j = 0; j < 6; j++)
            *reinterpret_cast<uint2*>(base + j * IN_F) = *reinterpret_cast<uint2*>(o[j]);
    }
}

// ---- kernel 2: high-occupancy fp16 GEMM, interleaved fill -------------------
__global__ void __launch_bounds__(256, 3) gemm_kernel(float* __restrict__ out) {
    extern __shared__ __align__(16) char dsm[];
    const int tid = threadIdx.x, lane = tid & 31, wid = tid >> 5;
    const int wm = wid & 1, wn = wid >> 1;      // 2(m) x 4(n) warps, 32x32 tiles
    const int bn = blockIdx.x, bm = blockIdx.y;

    const __half* gA = g_F + (size_t)(bm * BM) * KDIM;
    const __half* gB = g_W + (size_t)(bn * BN) * KDIM;
    const uint32_t s0 = smem_u32(dsm);

    // ---- loader geometry ----------------------------------------------------
    uint32_t sAoff[2], sBoff[4];
    uint32_t gAoff[2], gBoff[4];
#pragma unroll
    for (int c = 0; c < 2; c++) {
        int chunk = tid + 256 * c;
        int row = chunk >> 3, ch = chunk & 7;
        sAoff[c] = (uint32_t)(row * ROWB + ((ch ^ (row & 7)) << 4));
        gAoff[c] = (uint32_t)(row * KDIM + ch * 8);
    }
#pragma unroll
    for (int c = 0; c < 4; c++) {
        int chunk = tid + 256 * c;
        int row = chunk >> 3, ch = chunk & 7;
        sBoff[c] = (uint32_t)(A_BYTES + row * ROWB + ((ch ^ (row & 7)) << 4));
        gBoff[c] = (uint32_t)(row * KDIM + ch * 8);
    }

    // ---- ldmatrix geometry ---------------------------------------------------
    const int frow = lane & 15;
    const int hi   = lane >> 4;
    const int sw   = lane & 7;
    uint32_t xb[4];
#pragma unroll
    for (int kk = 0; kk < 4; kk++)
        xb[kk] = (uint32_t)(((2 * kk + hi) ^ sw) << 4);
    uint32_t aRow[2], bRow[2];
#pragma unroll
    for (int mf = 0; mf < 2; mf++)
        aRow[mf] = s0 + (uint32_t)((wm * 32 + mf * 16 + frow) * ROWB);
#pragma unroll
    for (int nb = 0; nb < 2; nb++)
        bRow[nb] = s0 + (uint32_t)(A_BYTES + (wn * 32 + nb * 16 + frow) * ROWB);

    float acc[2][4][4];
#pragma unroll
    for (int i = 0; i < 2; i++)
#pragma unroll
        for (int j = 0; j < 4; j++)
#pragma unroll
            for (int r = 0; r < 4; r++) acc[i][j][r] = 0.0f;

// full fill (prologue only)
#define FILL(s, kt) do { \
    uint32_t b_ = s0 + (s) * STAGE_B; \
    const __half* a0_ = gA + (size_t)(kt) * BK; \
    const __half* b0_ = gB + (size_t)(kt) * BK; \
    _Pragma("unroll") \
    for (int c_ = 0; c_ < 2; c_++) cp_async16(b_ + sAoff[c_], a0_ + gAoff[c_]); \
    _Pragma("unroll") \
    for (int c_ = 0; c_ < 4; c_++) cp_async16(b_ + sBoff[c_], b0_ + gBoff[c_]); \
    CP_COMMIT(); \
} while (0)

// partial fills (steady state)
#define FILL_A(s, kt) do { \
    uint32_t b_ = s0 + (s) * STAGE_B; \
    const __half* a0_ = gA + (size_t)(kt) * BK; \
    cp_async16(b_ + sAoff[0], a0_ + gAoff[0]); \
    cp_async16(b_ + sAoff[1], a0_ + gAoff[1]); \
} while (0)
#define FILL_B01(s, kt) do { \
    uint32_t b_ = s0 + (s) * STAGE_B; \
    const __half* b0_ = gB + (size_t)(kt) * BK; \
    cp_async16(b_ + sBoff[0], b0_ + gBoff[0]); \
    cp_async16(b_ + sBoff[1], b0_ + gBoff[1]); \
} while (0)
#define FILL_B23(s, kt) do { \
    uint32_t b_ = s0 + (s) * STAGE_B; \
    const __half* b0_ = gB + (size_t)(kt) * BK; \
    cp_async16(b_ + sBoff[2], b0_ + gBoff[2]); \
    cp_async16(b_ + sBoff[3], b0_ + gBoff[3]); \
} while (0)

    uint32_t af[2][4], bf[2][4];

#define STEP(kk, soff) do { \
    _Pragma("unroll") \
    for (int mf_ = 0; mf_ < 2; mf_++) ldsm4(af[mf_], aRow[mf_] + (soff) + xb[kk]); \
    _Pragma("unroll") \
    for (int nb_ = 0; nb_ < 2; nb_++) ldsm4(bf[nb_], bRow[nb_] + (soff) + xb[kk]); \
    _Pragma("unroll") \
    for (int mf_ = 0; mf_ < 2; mf_++) \
        _Pragma("unroll") \
        for (int nf_ = 0; nf_ < 4; nf_++) \
            mma16816(acc[mf_][nf_], af[mf_], \
                     bf[nf_ >> 1][nf_ & 1], bf[nf_ >> 1][(nf_ & 1) + 2]); \
} while (0)

    FILL(0, 0);
    FILL(1, 1);

#pragma unroll 1
    for (int kt = 0; kt < KTILES; kt++) {
        if (kt == KTILES - 1) { CP_WAIT(0); } else { CP_WAIT(1); }
        __syncthreads();

        const uint32_t soff = (uint32_t)((kt % NSTG) * STAGE_B);
        const int fs = (kt + 2) % NSTG;
        const bool doFill = (kt + 2 < KTILES);

        STEP(0, soff);
        if (doFill) FILL_A(fs, kt + 2);
        STEP(1, soff);
        if (doFill) FILL_B01(fs, kt + 2);
        STEP(2, soff);
        if (doFill) { FILL_B23(fs, kt + 2); }
        CP_COMMIT();
        STEP(3, soff);
    }

    // ---- epilogue ---------------------------------------------------------------
#pragma unroll
    for (int mf = 0; mf < 2; mf++) {
        int r0 = bm * BM + wm * 32 + mf * 16 + (lane >> 2);
#pragma unroll
        for (int nf = 0; nf < 4; nf++) {
            int col = bn * BN + wn * 32 + nf * 8 + (lane & 3) * 2;
            float2 bv = *reinterpret_cast<const float2*>(&g_bias[col]);
            float2 v0 = make_float2(acc[mf][nf][0] + bv.x, acc[mf][nf][1] + bv.y);
            float2 v1 = make_float2(acc[mf][nf][2] + bv.x, acc[mf][nf][3] + bv.y);
            *reinterpret_cast<float2*>(out + (size_t)r0 * OUT_F + col)       = v0;
            *reinterpret_cast<float2*>(out + (size_t)(r0 + 8) * OUT_F + col) = v1;
        }
    }
}

// ---------------- launch ----------------------------------------------------
extern "C" void kernel_launch(void* const* d_in, const int* in_sizes, int n_in,
                              void* d_out, int out_size) {
    (void)in_sizes; (void)n_in; (void)out_size;
    const float* x    = (const float*)d_in[0];
    const float* bw   = (const float*)d_in[1];
    const float* jc   = (const float*)d_in[2];
    const float* bias = (const float*)d_in[3];
    float* out = (float*)d_out;

    cudaFuncSetAttribute(gemm_kernel, cudaFuncAttributeMaxDynamicSharedMemorySize, DYN_SMEM);

    prep_kernel<<<1024 + (BATCH * IN_F / 4) / 256, 256>>>(x, bw, jc, bias);
    dim3 grid(OUT_F / BN, BATCH / BM);   // (8, 128) = 1024 CTAs
    gemm_kernel<<<grid, 256, DYN_SMEM>>>(out);
}